// round 1
// baseline (speedup 1.0000x reference)
#include <cuda_runtime.h>

// WKV7 (RWKV-7) recurrence, T=4096, H=32, N=64.
// Design: warp-per-row. Each of the H*N = 2048 state rows evolves
// independently; one warp owns one row, each lane holds 2 state elements
// (j = 2*lane, 2*lane+1). Per timestep:
//   sa   = sum_j s[j]*a_t[j]          (5-level shfl_xor butterfly)
//   s[j] = s[j]*w_t[j] + sa*b_t[j] + v_t[i]*k_t[j]
//   y    = sum_j s[j]*r_t[j]          (5-level shfl_xor butterfly)
// Inputs for t+1 are prefetched while computing step t.

#define TT 4096
#define HH 32
#define NN 64
#define CC (HH * NN)  // 2048 channels per timestep

__global__ __launch_bounds__(32) void wkv7_scan_kernel(
    const float* __restrict__ r, const float* __restrict__ w,
    const float* __restrict__ k, const float* __restrict__ v,
    const float* __restrict__ a, const float* __restrict__ b,
    const float* __restrict__ s0, float* __restrict__ out)
{
    const int row  = blockIdx.x;        // 0..2047  == h*64 + i
    const int h    = row >> 6;
    const int i    = row & 63;
    const int lane = threadIdx.x;       // 0..31
    const int j0   = lane << 1;

    // Load initial state row: s0[h, i, j0], s0[h, i, j0+1]
    float2 s = *reinterpret_cast<const float2*>(s0 + ((size_t)(h * NN + i) * NN + j0));

    const int vecbase = h * NN + j0;    // per-timestep offset for the j-vectors
    const int vibase  = h * NN + i;     // per-timestep offset for v_i and y_i

    // Prefetch t = 0
    float2 A = *reinterpret_cast<const float2*>(a + vecbase);
    float2 W = *reinterpret_cast<const float2*>(w + vecbase);
    float2 K = *reinterpret_cast<const float2*>(k + vecbase);
    float2 B = *reinterpret_cast<const float2*>(b + vecbase);
    float2 R = *reinterpret_cast<const float2*>(r + vecbase);
    float  V = v[vibase];

    #pragma unroll 1
    for (int t = 0; t < TT; ++t) {
        // ---- prefetch t+1 (clamped; redundant reload of last step is harmless)
        const int tn = (t + 1 < TT) ? (t + 1) : t;
        const size_t noff = (size_t)tn * CC + vecbase;
        float2 An = *reinterpret_cast<const float2*>(a + noff);
        float2 Wn = *reinterpret_cast<const float2*>(w + noff);
        float2 Kn = *reinterpret_cast<const float2*>(k + noff);
        float2 Bn = *reinterpret_cast<const float2*>(b + noff);
        float2 Rn = *reinterpret_cast<const float2*>(r + noff);
        float  Vn = v[(size_t)tn * CC + vibase];

        // ---- sa = s_{t-1} . a_t  (uses state BEFORE update)
        float p = fmaf(s.x, A.x, s.y * A.y);
        p += __shfl_xor_sync(0xffffffffu, p, 16);
        p += __shfl_xor_sync(0xffffffffu, p, 8);
        p += __shfl_xor_sync(0xffffffffu, p, 4);
        p += __shfl_xor_sync(0xffffffffu, p, 2);
        p += __shfl_xor_sync(0xffffffffu, p, 1);

        // ---- state update: s = s*w + v_i*k + sa*b
        s.x = fmaf(p, B.x, fmaf(V, K.x, s.x * W.x));
        s.y = fmaf(p, B.y, fmaf(V, K.y, s.y * W.y));

        // ---- y = s_t . r_t
        float q = fmaf(s.x, R.x, s.y * R.y);
        q += __shfl_xor_sync(0xffffffffu, q, 16);
        q += __shfl_xor_sync(0xffffffffu, q, 8);
        q += __shfl_xor_sync(0xffffffffu, q, 4);
        q += __shfl_xor_sync(0xffffffffu, q, 2);
        q += __shfl_xor_sync(0xffffffffu, q, 1);
        if (lane == 0) {
            out[(size_t)t * CC + vibase] = q;
        }

        // rotate prefetch buffers
        A = An; W = Wn; K = Kn; B = Bn; R = Rn; V = Vn;
    }

    // ---- final state: out[T*C + h*N*N + i*N + j0 ...]
    *reinterpret_cast<float2*>(out + (size_t)TT * CC +
                               ((size_t)(h * NN + i) * NN + j0)) = s;
}

// Input order (metadata): seq_length(int32), r, w, k, v, a, b, state2.
// Output: concat(x[T,H,1,N], state2_out[H,N,N]) as float32.
extern "C" void kernel_launch(void* const* d_in, const int* in_sizes, int n_in,
                              void* d_out, int out_size)
{
    const float* r  = (const float*)d_in[1];
    const float* w  = (const float*)d_in[2];
    const float* k  = (const float*)d_in[3];
    const float* v  = (const float*)d_in[4];
    const float* a  = (const float*)d_in[5];
    const float* b  = (const float*)d_in[6];
    const float* s0 = (const float*)d_in[7];
    float* out = (float*)d_out;

    wkv7_scan_kernel<<<HH * NN, 32>>>(r, w, k, v, a, b, s0, out);
}